// round 1
// baseline (speedup 1.0000x reference)
#include <cuda_runtime.h>
#include <stdint.h>

// Problem constants
#define NB       64
#define NH       512
#define NW       512
#define NC       3
#define NPH      64
#define NPW      64
#define NP_TOT   4096          // patches per image
#define NUM_MASK 3072          // masked patches per image

// Per-image patch keep-mask: 1 = keep, 0 = zero out. 64 * 4096 = 256 KB.
__device__ uint8_t g_keep[NB * NP_TOT];

// ---------------------------------------------------------------------------
// Kernel 1: set all mask bytes to 1 (vectorized 16B stores).
// 262144 bytes / 16 = 16384 uint4 stores.
__global__ void init_mask_kernel() {
    int i = blockIdx.x * blockDim.x + threadIdx.x;
    ((uint4*)g_keep)[i] = make_uint4(0x01010101u, 0x01010101u,
                                     0x01010101u, 0x01010101u);
}

// ---------------------------------------------------------------------------
// Kernel 2: scatter zeros at masked patch indices.
// mask_indices: [NB, NUM_MASK] int32, each row is a slice of a permutation
// (no duplicates within an image) -> plain byte stores, no atomics needed.
__global__ void scatter_mask_kernel(const int* __restrict__ mask_indices) {
    int i = blockIdx.x * blockDim.x + threadIdx.x;
    if (i < NB * NUM_MASK) {
        int b   = i / NUM_MASK;
        int idx = mask_indices[i];
        g_keep[b * NP_TOT + idx] = 0;
    }
}

// ---------------------------------------------------------------------------
// Kernel 3: apply the mask.
// One thread = one float4 (16B). Patch width in floats = 8*3 = 24, and
// 4 | 24, so each aligned float4 lies entirely inside one patch column.
// Masked patches: store zeros WITHOUT loading the image (saves ~75% of
// read traffic; this kernel is purely HBM-bound).
__global__ void apply_mask_kernel(const float4* __restrict__ img,
                                  float4* __restrict__ out) {
    const int F4_PER_IMG = NH * NW * NC / 4;   // 196608
    const int F4_PER_ROW = NW * NC / 4;        // 384

    int i = blockIdx.x * blockDim.x + threadIdx.x;   // [0, NB*F4_PER_IMG)

    int b   = i / F4_PER_IMG;
    int r   = i - b * F4_PER_IMG;
    int row = r / F4_PER_ROW;                  // [0, 512)
    int c4  = r - row * F4_PER_ROW;            // [0, 384)

    int patch_y = row >> 3;                    // row / 8
    int patch_x = c4 / 6;                      // (c4*4)/24
    int pid     = (patch_y << 6) | patch_x;    // patch_y*64 + patch_x

    uint8_t keep = g_keep[(b << 12) | pid];

    if (keep) {
        out[i] = img[i];
    } else {
        out[i] = make_float4(0.f, 0.f, 0.f, 0.f);
    }
}

// ---------------------------------------------------------------------------
extern "C" void kernel_launch(void* const* d_in, const int* in_sizes, int n_in,
                              void* d_out, int out_size) {
    const float4* img = (const float4*)d_in[0];       // images [64,512,512,3] f32
    const int* mask_indices = (const int*)d_in[1];    // [64, 3072] i32
    float4* out = (float4*)d_out;

    // 1) init mask to ones: 16384 uint4 stores
    init_mask_kernel<<<64, 256>>>();

    // 2) scatter zeros: 196608 threads
    scatter_mask_kernel<<<(NB * NUM_MASK + 255) / 256, 256>>>(mask_indices);

    // 3) apply: 12,582,912 float4 threads
    const int total_f4 = NB * NH * NW * NC / 4;
    apply_mask_kernel<<<total_f4 / 256, 256>>>(img, out);
}

// round 2
// speedup vs baseline: 1.1256x; 1.1256x over previous
#include <cuda_runtime.h>
#include <stdint.h>

// Problem constants
#define NB       64
#define NH       512
#define NW       512
#define NC       3
#define NP_TOT   4096          // patches per image (64x64)
#define NUM_MASK 3072          // masked patches per image

// Per-image patch keep-mask: 1 = keep, 0 = zero out. 64 * 4096 = 256 KB.
__device__ uint8_t g_keep[NB * NP_TOT];

// ---------------------------------------------------------------------------
// Kernel 1 (fused init + scatter): one block per image, 1024 threads.
// Phase 1: init this image's 4096 mask bytes to 1 (one u32 per thread).
// Phase 2: after __syncthreads, scatter zeros at this image's 3072 masked
// indices (3 per thread). All ordering is intra-block -> correct.
__global__ void build_mask_kernel(const int* __restrict__ mask_indices) {
    const int b = blockIdx.x;
    const int t = threadIdx.x;

    // init: 4096 bytes = 1024 u32
    ((uint32_t*)g_keep)[b * 1024 + t] = 0x01010101u;
    __syncthreads();

    // scatter: 3072 indices, 3 per thread (permutation slice: no duplicates)
    const int* mi = mask_indices + b * NUM_MASK;
    uint8_t* keep = g_keep + b * NP_TOT;
#pragma unroll
    for (int j = 0; j < 3; j++) {
        keep[mi[t + j * 1024]] = 0;
    }
}

// ---------------------------------------------------------------------------
// Kernel 2: apply the mask.
// Grid (NH, NB): one block per image row. 384 threads = 384 float4 = one
// full row (512 px * 3 ch * 4B = 6144 B). Each float4 lies within exactly
// one patch column (24 floats per patch, 4 | 24 -> t/6 selects the patch).
// Masked patches: store zeros WITHOUT loading the image (saves ~75% of
// read traffic). Streaming hints: data has zero reuse.
__global__ void __launch_bounds__(384)
apply_mask_kernel(const float4* __restrict__ img, float4* __restrict__ out) {
    const int row = blockIdx.x;           // [0, 512)
    const int b   = blockIdx.y;           // [0, 64)
    const int t   = threadIdx.x;          // [0, 384)

    const int pid = ((row >> 3) << 6) | (t / 6);     // patch id within image
    const uint8_t keep = g_keep[(b << 12) | pid];

    const int i = (b * NH + row) * 384 + t;          // float4 index

    float4 v = make_float4(0.f, 0.f, 0.f, 0.f);
    if (keep) v = __ldcs(img + i);
    __stcs(out + i, v);
}

// ---------------------------------------------------------------------------
extern "C" void kernel_launch(void* const* d_in, const int* in_sizes, int n_in,
                              void* d_out, int out_size) {
    const float4* img = (const float4*)d_in[0];       // images [64,512,512,3] f32
    const int* mask_indices = (const int*)d_in[1];    // [64, 3072] i32
    float4* out = (float4*)d_out;

    // 1) build keep-mask: one block per image
    build_mask_kernel<<<NB, 1024>>>(mask_indices);

    // 2) apply: one block per image row
    dim3 grid(NH, NB);
    apply_mask_kernel<<<grid, 384>>>(img, out);
}

// round 3
// speedup vs baseline: 1.3989x; 1.2428x over previous
#include <cuda_runtime.h>
#include <stdint.h>

// Problem constants
#define NB       64
#define NH       512
#define NW       512
#define NC       3
#define NP_TOT   4096          // patches per image (64x64)
#define NUM_MASK 3072          // masked patches per image

// Per-image patch keep-mask: 1 = keep, 0 = zero out. 64 * 4096 = 256 KB.
__device__ uint8_t g_keep[NB * NP_TOT];

// ---------------------------------------------------------------------------
// Kernel 1 (fused init + scatter): one block per image, 1024 threads.
// Phase 1: init this image's 4096 mask bytes to 1 (one u32 per thread).
// Phase 2: after __syncthreads, scatter zeros at this image's 3072 masked
// indices (3 per thread). All ordering is intra-block -> correct.
__global__ void build_mask_kernel(const int* __restrict__ mask_indices) {
    const int b = blockIdx.x;
    const int t = threadIdx.x;

    // init: 4096 bytes = 1024 u32
    ((uint32_t*)g_keep)[b * 1024 + t] = 0x01010101u;
    __syncthreads();

    // scatter: 3072 indices, 3 per thread (permutation slice: no duplicates)
    const int* mi = mask_indices + b * NUM_MASK;
    uint8_t* keep = g_keep + b * NP_TOT;
#pragma unroll
    for (int j = 0; j < 3; j++) {
        keep[mi[t + j * 1024]] = 0;
    }
}

// ---------------------------------------------------------------------------
// Kernel 2: apply the mask.
// Grid (NPH=64 patch-rows, NB=64 images); block = 384 threads.
// A patch spans 8 consecutive image rows and shares ONE mask byte, so each
// thread owns one float4 column across the 8 rows of its patch band:
//   - 1 mask byte load
//   - keep: 8x LDG.128 (front-batched -> MLP=8) + 8x STG.128
//   - drop: 8x STG.128 of zeros, image never read (saves 75% read traffic)
// Consecutive threads touch consecutive float4s within a row -> fully
// coalesced. Row stride = 384 float4 = 6144 B.
__global__ void __launch_bounds__(384)
apply_mask_kernel(const float4* __restrict__ img, float4* __restrict__ out) {
    const int pr = blockIdx.x;            // patch row   [0, 64)
    const int b  = blockIdx.y;            // image       [0, 64)
    const int t  = threadIdx.x;           // float4 col  [0, 384)

    const int pid = (pr << 6) | (t / 6);  // 24 floats (6 float4) per patch col
    const uint8_t keep = g_keep[(b << 12) | pid];

    const long base = ((long)(b * NH + (pr << 3)) * 384) + t;
    const float4* ip = img + base;
    float4*       op = out + base;

    if (keep) {
        float4 v[8];
#pragma unroll
        for (int r = 0; r < 8; r++) v[r] = __ldcs(ip + r * 384);
#pragma unroll
        for (int r = 0; r < 8; r++) __stcs(op + r * 384, v[r]);
    } else {
        const float4 z = make_float4(0.f, 0.f, 0.f, 0.f);
#pragma unroll
        for (int r = 0; r < 8; r++) __stcs(op + r * 384, z);
    }
}

// ---------------------------------------------------------------------------
extern "C" void kernel_launch(void* const* d_in, const int* in_sizes, int n_in,
                              void* d_out, int out_size) {
    const float4* img = (const float4*)d_in[0];       // images [64,512,512,3] f32
    const int* mask_indices = (const int*)d_in[1];    // [64, 3072] i32
    float4* out = (float4*)d_out;

    // 1) build keep-mask: one block per image
    build_mask_kernel<<<NB, 1024>>>(mask_indices);

    // 2) apply: one block per (patch-row, image) band
    dim3 grid(64, NB);
    apply_mask_kernel<<<grid, 384>>>(img, out);
}

// round 4
// speedup vs baseline: 1.5060x; 1.0766x over previous
#include <cuda_runtime.h>
#include <stdint.h>

// Problem constants
#define NB       64
#define NH       512
#define NW       512
#define NC       3
#define NUM_MASK 3072          // masked patches per image

// ---------------------------------------------------------------------------
// Single fused kernel.
// Grid (NPH=64 patch-rows, NB=64 images); block = 384 threads.
//
// Prologue: build this block's 64-patch keep bitmap directly from
// mask_indices (no intermediate global mask, no builder kernel):
//   - each thread reads 8 indices of this image's 3072 (coalesced; the
//     12 KB slice is shared by 64 blocks -> L2 resident)
//   - range-test against this patch-row, atomicOr into 2 shared words.
//
// Main: a patch spans 8 consecutive rows sharing one mask bit. Each thread
// owns one float4 column across the 8 rows of its patch band:
//   - keep: 8x LDG.128 (front-batched -> MLP=8) + 8x STG.128
//   - drop: 8x STG.128 of zeros, image never read (saves 75% read traffic)
// Consecutive threads touch consecutive float4s within a row -> fully
// coalesced. Row stride = 384 float4 = 6144 B.
__global__ void __launch_bounds__(384)
random_mask_kernel(const float4* __restrict__ img,
                   const int*    __restrict__ mask_indices,
                   float4*       __restrict__ out) {
    const int pr = blockIdx.x;            // patch row   [0, 64)
    const int b  = blockIdx.y;            // image       [0, 64)
    const int t  = threadIdx.x;           // float4 col  [0, 384)

    // ---- build 64-bit masked-bitmap for this (image, patch-row) ----
    __shared__ uint32_t masked_bits[2];
    if (t < 2) masked_bits[t] = 0;
    __syncthreads();

    const int* mi = mask_indices + b * NUM_MASK;
    const int lo = pr << 6;               // first patch id of this row
#pragma unroll
    for (int j = 0; j < 8; j++) {
        int idx = mi[t + j * 384];        // coalesced, L2-resident
        unsigned d = (unsigned)(idx - lo);
        if (d < 64u) atomicOr(&masked_bits[d >> 5], 1u << (d & 31));
    }
    __syncthreads();

    const int p = t / 6;                  // patch col: 6 float4 per patch
    const bool keep = !((masked_bits[p >> 5] >> (p & 31)) & 1u);

    // ---- stream the 8-row band ----
    const long base = ((long)(b * NH + (pr << 3)) * 384) + t;
    const float4* ip = img + base;
    float4*       op = out + base;

    if (keep) {
        float4 v[8];
#pragma unroll
        for (int r = 0; r < 8; r++) v[r] = __ldcs(ip + r * 384);
#pragma unroll
        for (int r = 0; r < 8; r++) __stcs(op + r * 384, v[r]);
    } else {
        const float4 z = make_float4(0.f, 0.f, 0.f, 0.f);
#pragma unroll
        for (int r = 0; r < 8; r++) __stcs(op + r * 384, z);
    }
}

// ---------------------------------------------------------------------------
extern "C" void kernel_launch(void* const* d_in, const int* in_sizes, int n_in,
                              void* d_out, int out_size) {
    const float4* img = (const float4*)d_in[0];       // images [64,512,512,3] f32
    const int* mask_indices = (const int*)d_in[1];    // [64, 3072] i32
    float4* out = (float4*)d_out;

    dim3 grid(64, NB);                    // (patch-rows, images)
    random_mask_kernel<<<grid, 384>>>(img, mask_indices, out);
}